// round 16
// baseline (speedup 1.0000x reference)
#include <cuda_runtime.h>
#include <math.h>

#define NBOARD 13
#define SN 169
#define NG 2048
#define NT 192
#define GGRID 296         // 2 CTAs per SM
#define EPSV 1e-5f
#define LSMIN -5.0f
#define LSMAX 2.0f

#define HSF 78            // h row stride (floats): FEAT [0,36), AGG [40,76)
#define HSU 39
#define AOFF 40
#define AOFFU 20
#define OSF 38

typedef unsigned long long ull;

__device__ __forceinline__ ull pk2(float x, float y) {
    ull r; asm("mov.b64 %0, {%1,%2};" : "=l"(r) : "f"(x), "f"(y)); return r;
}
__device__ __forceinline__ float2 upk2(ull a) {
    float2 v; asm("mov.b64 {%0,%1}, %2;" : "=f"(v.x), "=f"(v.y) : "l"(a)); return v;
}
__device__ __forceinline__ ull ffma2(ull a, ull b, ull c) {
    ull d; asm("fma.rn.f32x2 %0, %1, %2, %3;" : "=l"(d) : "l"(a), "l"(b), "l"(c)); return d;
}
__device__ __forceinline__ ull fadd2(ull a, ull b) {
    ull d; asm("add.rn.f32x2 %0, %1, %2;" : "=l"(d) : "l"(a), "l"(b)); return d;
}
__device__ __forceinline__ ull fmul2(ull a, ull b) {
    ull d; asm("mul.rn.f32x2 %0, %1, %2;" : "=l"(d) : "l"(a), "l"(b)); return d;
}

__device__ float g_pooled[NG * 72];

struct __align__(16) Smem {
    float wc3[36 * 72];
    float wr2[36 * 72];
    float wc2[18 * 36];
    float wr1[18 * 36];
    float E1[56];
    float embs[56];
    float bc1[18], bc2[36], bc3[72];
    float br1[36], br2[72];
    float g1v[18], be1v[18], a1v[18];
    float g2v[36], be2v[36], a2v[36];
    float g3v[72], be3v[72], a3v[72];
    float redP[192], redQ[192];
    float redS[72], redC[72];
    float dis[170];
    float h[SN * HSF];       // single graph
    float out[SN * OSF];
};

__device__ __forceinline__ void cp_sm(float* dst, const float* src, int n, int t) {
    for (int i = t; i < n; i += NT) dst[i] = src[i];
}

// packed gather (conflict-free: HSU=39 odd)
template<int WU>
__device__ __forceinline__ void gatherU(const ull* base, const ull* own, ull* dst,
                                        const int* nbU, const ull* dnb2, ull dd) {
    #pragma unroll 3
    for (int k = 0; k < WU; k++) {
        ull a = fmul2(own[k], dd);
        #pragma unroll
        for (int j = 0; j < 6; j++) a = ffma2(dnb2[j], base[nbU[j] + k], a);
        dst[k] = fmul2(a, dd);
    }
}

// acc[0:18) += in @ W (36-wide output slice), weights broadcast from smem
template<int K, int RS>
__device__ __forceinline__ void mm1(const float* W0, const float* in, ull* acc) {
    #pragma unroll 2
    for (int k = 0; k < K; k++) {
        const float a = in[k];
        const ull q = pk2(a, a);
        const ulonglong2* w = (const ulonglong2*)(W0 + k * RS);
        #pragma unroll
        for (int jv = 0; jv < 9; jv++) {
            ulonglong2 ww = w[jv];
            acc[2 * jv]     = ffma2(q, ww.x, acc[2 * jv]);
            acc[2 * jv + 1] = ffma2(q, ww.y, acc[2 * jv + 1]);
        }
    }
}

// stats over out rows: Wf features x NS stripes
__device__ __forceinline__ void stat1(Smem& sm, int t, int Wf, int NS) {
    if (t < Wf * NS) {
        const int f = t % Wf, sI = t / Wf;
        float s = 0.f, s2 = 0.f;
        const float* pp = sm.out + f;
        for (int n = sI; n < SN; n += NS) { float v = pp[n * OSF]; s += v; s2 = fmaf(v, v, s2); }
        sm.redP[t] = s; sm.redQ[t] = s2;
    }
}

__device__ __forceinline__ void sc1(Smem& sm, int t, int Wf, int NS,
                                    const float* gv, const float* bev, const float* av) {
    const float invS = 1.0f / (float)SN;
    if (t < Wf) {
        float s = 0.f, s2 = 0.f;
        for (int i = 0; i < NS; i++) { s += sm.redP[t + i * Wf]; s2 += sm.redQ[t + i * Wf]; }
        float m = s * invS, af = av[t];
        float var = s2 * invS - m * m * af * (2.0f - af);
        float S = gv[t] * rsqrtf(var + EPSV);
        sm.redS[t] = S; sm.redC[t] = bev[t] - af * m * S;
    }
}

__global__ void __launch_bounds__(NT, 2) gnn_kernel(
    const int* __restrict__ x,
    const float* __restrict__ emb,
    const float* __restrict__ wc1, const float* __restrict__ bc1,
    const float* __restrict__ wc2, const float* __restrict__ bc2,
    const float* __restrict__ wc3, const float* __restrict__ bc3,
    const float* __restrict__ wr1, const float* __restrict__ br1,
    const float* __restrict__ wr2, const float* __restrict__ br2,
    const float* __restrict__ g1, const float* __restrict__ be1, const float* __restrict__ a1,
    const float* __restrict__ g2, const float* __restrict__ be2, const float* __restrict__ a2,
    const float* __restrict__ g3, const float* __restrict__ be3, const float* __restrict__ a3)
{
    extern __shared__ char smraw[];
    Smem& sm = *reinterpret_cast<Smem*>(smraw);
    const int t = threadIdx.x;
    const bool isNode = (t < SN);
    ull* const hU = (ull*)sm.h;
    const float invS = 1.0f / (float)SN;

    cp_sm(sm.wc3, wc3, 36 * 72, t);
    cp_sm(sm.wr2, wr2, 36 * 72, t);
    cp_sm(sm.wc2, wc2, 18 * 36, t);
    cp_sm(sm.wr1, wr1, 18 * 36, t);
    cp_sm(sm.bc1, bc1, 18, t);  cp_sm(sm.bc2, bc2, 36, t);  cp_sm(sm.bc3, bc3, 72, t);
    cp_sm(sm.br1, br1, 36, t);  cp_sm(sm.br2, br2, 72, t);
    cp_sm(sm.g1v, g1, 18, t);   cp_sm(sm.be1v, be1, 18, t); cp_sm(sm.a1v, a1, 18, t);
    cp_sm(sm.g2v, g2, 36, t);   cp_sm(sm.be2v, be2, 36, t); cp_sm(sm.a2v, a2, 36, t);
    cp_sm(sm.g3v, g3, 72, t);   cp_sm(sm.be3v, be3, 72, t); cp_sm(sm.a3v, a3, 72, t);
    cp_sm(sm.embs, emb, 3 * 18, t);

    if (t < 54) {
        const int e = t / 18, j = t % 18;
        float s = 0.f;
        #pragma unroll
        for (int k = 0; k < 18; k++) s += emb[e * 18 + k] * wc1[k * 18 + j];
        sm.E1[e * 18 + j] = s;
    }

    int nbU[6], nbi[6];
    ull dnb2[6];
    float disn = 0.f;
    if (isNode) {
        const int r = t / NBOARD, c = t % NBOARD;
        const int drr[6] = { -1, 1, 0, 0, -1, 1 };
        const int dcc[6] = { 0, 0, -1, 1, 1, -1 };
        int deg = 1;
        #pragma unroll
        for (int j = 0; j < 6; j++) {
            int rr = r + drr[j], cc = c + dcc[j];
            if (rr >= 0 && rr < NBOARD && cc >= 0 && cc < NBOARD) { nbi[j] = rr * NBOARD + cc; deg++; }
            else nbi[j] = t;
            nbU[j] = nbi[j] * HSU;
        }
        disn = rsqrtf((float)deg);
        sm.dis[t] = disn;
    }
    __syncthreads();
    if (isNode) {
        #pragma unroll
        for (int j = 0; j < 6; j++) {
            const float d = (nbi[j] == t) ? 0.f : sm.dis[nbi[j]];
            dnb2[j] = pk2(d, d);
        }
    }
    __syncthreads();

    const ull dd = pk2(disn, disn);
    float* const hA = sm.h + t * HSF;
    ull* const haU = hU + t * HSU;
    float* const oA = sm.out + t * OSF;

    // prefetch first graph's x
    int xnext = 0;
    if (isNode && blockIdx.x < NG) xnext = x[blockIdx.x * SN + t];

    for (int g = blockIdx.x; g < NG; g += GGRID) {

        // ---- lookup: h <- E1[x], original embedding in regs; prefetch next x
        ull h0A[9];
        if (isNode) {
            const int xa = xnext;
            if (g + GGRID < NG) xnext = x[(g + GGRID) * SN + t];
            const ull* ea = (const ull*)&sm.embs[xa * 18];
            const ull* fa = (const ull*)&sm.E1[xa * 18];
            #pragma unroll
            for (int i = 0; i < 9; i++) { h0A[i] = ea[i]; haU[i] = fa[i]; }
        }
        __syncthreads();

        // ================= Layer 1: conv = gather(E1x) + bc1 ================
        ull cv1[9];
        if (isNode) {
            const ull* b1 = (const ull*)sm.bc1;
            ull aU[9];
            gatherU<9>(hU, haU, aU, nbU, dnb2, dd);
            ull* ouA = (ull*)oA;
            #pragma unroll
            for (int i = 0; i < 9; i++) { cv1[i] = fadd2(aU[i], b1[i]); ouA[i] = cv1[i]; }
        }
        __syncthreads();
        stat1(sm, t, 18, 10);
        __syncthreads();
        sc1(sm, t, 18, 10, sm.g1v, sm.be1v, sm.a1v);
        __syncthreads();
        if (isNode) {
            const ull* Su = (const ull*)sm.redS;
            const ull* Cu = (const ull*)sm.redC;
            #pragma unroll
            for (int i = 0; i < 9; i++)
                haU[i] = fadd2(ffma2(cv1[i], Su[i], Cu[i]), h0A[i]);
        }
        __syncthreads();

        // ================= Layer 2 (18->36) =================================
        ull accR[18], cv2[18];
        if (isNode) {
            gatherU<9>(hU, haU, haU + AOFFU, nbU, dnb2, dd);
            const ull* b2 = (const ull*)sm.bc2;
            #pragma unroll
            for (int i = 0; i < 18; i++) cv2[i] = b2[i];
            mm1<18, 36>(sm.wc2, hA + AOFF, cv2);
            ull* ouA = (ull*)oA;
            #pragma unroll
            for (int i = 0; i < 18; i++) ouA[i] = cv2[i];
            const ull* r1 = (const ull*)sm.br1;
            #pragma unroll
            for (int i = 0; i < 18; i++) accR[i] = r1[i];
            mm1<18, 36>(sm.wr1, hA, accR);
        }
        __syncthreads();
        stat1(sm, t, 36, 5);
        __syncthreads();
        sc1(sm, t, 36, 5, sm.g2v, sm.be2v, sm.a2v);
        __syncthreads();
        if (isNode) {
            const ull* Su = (const ull*)sm.redS;
            const ull* Cu = (const ull*)sm.redC;
            #pragma unroll
            for (int i = 0; i < 18; i++)
                haU[i] = fadd2(ffma2(cv2[i], Su[i], Cu[i]), accR[i]);
        }
        __syncthreads();

        // ========== Layer 3 (36->72): merged single pipeline (R14) ==========
        if (isNode) {
            gatherU<18>(hU, haU, haU + AOFFU, nbU, dnb2, dd);
            {
                ull acc[18];
                const ull* b3 = (const ull*)&sm.bc3[0];
                #pragma unroll
                for (int i = 0; i < 18; i++) acc[i] = b3[i];
                mm1<36, 72>(sm.wc3, hA + AOFF, acc);
                ull* ouA = (ull*)oA;
                #pragma unroll
                for (int i = 0; i < 18; i++) ouA[i] = acc[i];
            }
            {
                ull acc[18];
                const ull* b3 = (const ull*)&sm.bc3[36];
                #pragma unroll
                for (int i = 0; i < 18; i++) acc[i] = b3[i];
                mm1<36, 72>(sm.wc3 + 36, hA + AOFF, acc);
                ull* gAo = haU + AOFFU;
                #pragma unroll
                for (int i = 0; i < 18; i++) gAo[i] = acc[i];
            }
        }
        __syncthreads();
        // 72-wide stats, 2 stripes (144 threads)
        if (t < 144) {
            const int f = t % 72, sI = t / 72;
            const float* pp = (f < 36) ? (sm.out + f) : (sm.h + AOFF + (f - 36));
            const int str = (f < 36) ? OSF : HSF;
            float s = 0.f, s2 = 0.f;
            for (int n = sI; n < SN; n += 2) { float v = pp[n * str]; s += v; s2 = fmaf(v, v, s2); }
            sm.redP[t] = s; sm.redQ[t] = s2;
        }
        __syncthreads();
        if (t < 72) {
            float s = sm.redP[t] + sm.redP[t + 72];
            float s2 = sm.redQ[t] + sm.redQ[t + 72];
            float m = s * invS, af = sm.a3v[t];
            float var = s2 * invS - m * m * af * (2.0f - af);
            float S = sm.g3v[t] * rsqrtf(var + EPSV);
            sm.redS[t] = S; sm.redC[t] = sm.be3v[t] - af * m * S;
        }
        __syncthreads();
        // resid + apply, both halves (FEAT region intact as input)
        if (isNode) {
            {
                ull aR[18];
                const ull* r2 = (const ull*)&sm.br2[0];
                #pragma unroll
                for (int i = 0; i < 18; i++) aR[i] = r2[i];
                mm1<36, 72>(sm.wr2, hA, aR);
                ull* ouA = (ull*)oA;
                const ull* SA = (const ull*)sm.redS;
                const ull* CA = (const ull*)sm.redC;
                #pragma unroll
                for (int i = 0; i < 18; i++)
                    ouA[i] = fadd2(ffma2(ouA[i], SA[i], CA[i]), aR[i]);
            }
            {
                ull aR[18];
                const ull* r2 = (const ull*)&sm.br2[36];
                #pragma unroll
                for (int i = 0; i < 18; i++) aR[i] = r2[i];
                mm1<36, 72>(sm.wr2 + 36, hA, aR);
                ull* gAo = haU + AOFFU;
                const ull* SA = (const ull*)&sm.redS[36];
                const ull* CA = (const ull*)&sm.redC[36];
                #pragma unroll
                for (int i = 0; i < 18; i++)
                    gAo[i] = fadd2(ffma2(gAo[i], SA[i], CA[i]), aR[i]);
            }
        }
        __syncthreads();
        // pool: 2-stripe partials then final write
        if (t < 144) {
            const int f = t % 72, sI = t / 72;
            const float* pp = (f < 36) ? (sm.out + f) : (sm.h + AOFF + (f - 36));
            const int str = (f < 36) ? OSF : HSF;
            float m = -INFINITY;
            for (int n = sI; n < SN; n += 2) m = fmaxf(m, pp[n * str]);
            sm.redP[t] = m;
        }
        __syncthreads();
        if (t < 72) g_pooled[g * 72 + t] = fmaxf(sm.redP[t], sm.redP[t + 72]);
        __syncthreads();
    }
}

// ---------------------------------------------------------------------------
// MLP (proven 34.9us): TM=8, grid 256, 512 thr, split-k z2.
// ---------------------------------------------------------------------------
struct __align__(16) MSmem {
    ull rowsT[72][5];
    ull z1T[512][5];
    ull z2P[256][5];
    ull z2T[256][5];
};

__global__ void __launch_bounds__(512, 2) mlp_kernel(
    const float* __restrict__ wf1, const float* __restrict__ bf1,
    const float* __restrict__ wf2, const float* __restrict__ bf2,
    const float* __restrict__ wm, const float* __restrict__ bm,
    const float* __restrict__ wl, const float* __restrict__ bl,
    float* __restrict__ out)
{
    extern __shared__ char smraw[];
    MSmem& sm = *reinterpret_cast<MSmem*>(smraw);
    const int tid = threadIdx.x;
    const int r0 = blockIdx.x * 8;

    {
        float* rf = (float*)sm.rowsT;
        for (int i = tid; i < 8 * 72; i += 512) {
            const int k = i / 8, r = i % 8;
            rf[k * 10 + r] = g_pooled[(r0 + r) * 72 + k];
        }
    }
    __syncthreads();

    {
        const int j = tid;
        const float b = __ldg(bf1 + j);
        ull acc[4];
        #pragma unroll
        for (int i = 0; i < 4; i++) acc[i] = pk2(b, b);
        #pragma unroll 8
        for (int k = 0; k < 72; k++) {
            const float w = __ldg(wf1 + k * 512 + j);
            const ull ww = pk2(w, w);
            const ull* rw = sm.rowsT[k];
            #pragma unroll
            for (int i = 0; i < 4; i++) acc[i] = ffma2(ww, rw[i], acc[i]);
        }
        #pragma unroll
        for (int i = 0; i < 4; i++) {
            float2 v = upk2(acc[i]);
            sm.z1T[j][i] = pk2(fmaxf(v.x, 0.f), fmaxf(v.y, 0.f));
        }
    }
    __syncthreads();

    {
        const int jj = tid & 255, half = tid >> 8;
        ull acc[4];
        if (half == 0) {
            const float b = __ldg(bf2 + jj);
            #pragma unroll
            for (int i = 0; i < 4; i++) acc[i] = pk2(b, b);
        } else {
            #pragma unroll
            for (int i = 0; i < 4; i++) acc[i] = 0ull;
        }
        const int k0 = half * 256;
        #pragma unroll 8
        for (int kk = 0; kk < 256; kk++) {
            const int k = k0 + kk;
            const float w = __ldg(wf2 + k * 256 + jj);
            const ull ww = pk2(w, w);
            const ull* zw = sm.z1T[k];
            #pragma unroll
            for (int i = 0; i < 4; i++) acc[i] = ffma2(ww, zw[i], acc[i]);
        }
        if (half == 1) {
            #pragma unroll
            for (int i = 0; i < 4; i++) sm.z2P[jj][i] = acc[i];
        }
        __syncthreads();
        if (half == 0) {
            #pragma unroll
            for (int i = 0; i < 4; i++) {
                float2 v = upk2(fadd2(acc[i], sm.z2P[jj][i]));
                sm.z2T[jj][i] = pk2(fmaxf(v.x, 0.f), fmaxf(v.y, 0.f));
            }
        }
        __syncthreads();
    }

    {
        const int w = tid >> 5, lane = tid & 31;
        if (w < 8) {
            const int rp = w >> 1, hi = w & 1;
            float smv = 0.f, slv = 0.f;
            #pragma unroll 4
            for (int k = lane; k < 256; k += 32) {
                float2 v2 = upk2(sm.z2T[k][rp]);
                const float v = hi ? v2.y : v2.x;
                smv = fmaf(v, __ldg(wm + k), smv);
                slv = fmaf(v, __ldg(wl + k), slv);
            }
            #pragma unroll
            for (int o = 16; o > 0; o >>= 1) {
                smv += __shfl_xor_sync(0xffffffffu, smv, o);
                slv += __shfl_xor_sync(0xffffffffu, slv, o);
            }
            if (lane == 0) {
                out[r0 + w] = smv + __ldg(bm);
                const float ls = tanhf(slv + __ldg(bl));
                out[NG + r0 + w] = LSMIN + 0.5f * (LSMAX - LSMIN) * (ls + 1.0f);
            }
        }
    }
}

// ---------------------------------------------------------------------------
extern "C" void kernel_launch(void* const* d_in, const int* in_sizes, int n_in,
                              void* d_out, int out_size)
{
    const int*   x    = (const int*)d_in[0];
    const float* emb  = (const float*)d_in[2];
    const float* wc1  = (const float*)d_in[3];
    const float* bc1  = (const float*)d_in[4];
    const float* wc2  = (const float*)d_in[5];
    const float* bc2  = (const float*)d_in[6];
    const float* wc3  = (const float*)d_in[7];
    const float* bc3  = (const float*)d_in[8];
    const float* wr1  = (const float*)d_in[9];
    const float* br1  = (const float*)d_in[10];
    const float* wr2  = (const float*)d_in[11];
    const float* br2  = (const float*)d_in[12];
    const float* g1   = (const float*)d_in[13];
    const float* be1  = (const float*)d_in[14];
    const float* a1   = (const float*)d_in[15];
    const float* g2   = (const float*)d_in[16];
    const float* be2  = (const float*)d_in[17];
    const float* a2   = (const float*)d_in[18];
    const float* g3   = (const float*)d_in[19];
    const float* be3  = (const float*)d_in[20];
    const float* a3   = (const float*)d_in[21];
    const float* wf1  = (const float*)d_in[22];
    const float* bf1  = (const float*)d_in[23];
    const float* wf2  = (const float*)d_in[24];
    const float* bf2  = (const float*)d_in[25];
    const float* wm   = (const float*)d_in[26];
    const float* bm   = (const float*)d_in[27];
    const float* wl   = (const float*)d_in[28];
    const float* bl   = (const float*)d_in[29];
    float* out = (float*)d_out;

    cudaFuncSetAttribute(gnn_kernel, cudaFuncAttributeMaxDynamicSharedMemorySize,
                         (int)sizeof(Smem));
    cudaFuncSetAttribute(mlp_kernel, cudaFuncAttributeMaxDynamicSharedMemorySize,
                         (int)sizeof(MSmem));

    gnn_kernel<<<GGRID, NT, sizeof(Smem)>>>(
        x, emb, wc1, bc1, wc2, bc2, wc3, bc3, wr1, br1, wr2, br2,
        g1, be1, a1, g2, be2, a2, g3, be3, a3);

    mlp_kernel<<<NG / 8, 512, sizeof(MSmem)>>>(
        wf1, bf1, wf2, bf2, wm, bm, wl, bl, out);
}

// round 17
// speedup vs baseline: 1.1145x; 1.1145x over previous
#include <cuda_runtime.h>
#include <math.h>

#define NBOARD 13
#define SN 169
#define NG 2048
#define NT 192
#define GGRID 296         // 2 CTAs per SM
#define EPSV 1e-5f
#define LSMIN -5.0f
#define LSMAX 2.0f

#define HSF 78            // h row stride (floats): FEAT [0,36), AGG [40,76)
#define HSU 39
#define AOFF 40
#define AOFFU 20
#define OSF 38

typedef unsigned long long ull;

__device__ __forceinline__ ull pk2(float x, float y) {
    ull r; asm("mov.b64 %0, {%1,%2};" : "=l"(r) : "f"(x), "f"(y)); return r;
}
__device__ __forceinline__ float2 upk2(ull a) {
    float2 v; asm("mov.b64 {%0,%1}, %2;" : "=f"(v.x), "=f"(v.y) : "l"(a)); return v;
}
__device__ __forceinline__ ull ffma2(ull a, ull b, ull c) {
    ull d; asm("fma.rn.f32x2 %0, %1, %2, %3;" : "=l"(d) : "l"(a), "l"(b), "l"(c)); return d;
}
__device__ __forceinline__ ull fadd2(ull a, ull b) {
    ull d; asm("add.rn.f32x2 %0, %1, %2;" : "=l"(d) : "l"(a), "l"(b)); return d;
}
__device__ __forceinline__ ull fmul2(ull a, ull b) {
    ull d; asm("mul.rn.f32x2 %0, %1, %2;" : "=l"(d) : "l"(a), "l"(b)); return d;
}

__device__ float g_pooled[NG * 72];

struct __align__(16) Smem {
    float wc3[36 * 72];
    float wr2[36 * 72];
    float wc2[18 * 36];
    float wr1[18 * 36];
    float E1[56];
    float embs[56];
    float bc1[18], bc2[36], bc3[72];
    float br1[36], br2[72];
    float g1v[18], be1v[18], a1v[18];
    float g2v[36], be2v[36], a2v[36];
    float g3v[72], be3v[72], a3v[72];
    float redP[192], redQ[192];
    float redS[72], redC[72];
    float dis[170];
    float h[SN * HSF];       // single graph
    float out[SN * OSF];
};

__device__ __forceinline__ void cp_sm(float* dst, const float* src, int n, int t) {
    for (int i = t; i < n; i += NT) dst[i] = src[i];
}

// packed gather (conflict-free: HSU=39 odd)
template<int WU>
__device__ __forceinline__ void gatherU(const ull* base, const ull* own, ull* dst,
                                        const int* nbU, const ull* dnb2, ull dd) {
    #pragma unroll 3
    for (int k = 0; k < WU; k++) {
        ull a = fmul2(own[k], dd);
        #pragma unroll
        for (int j = 0; j < 6; j++) a = ffma2(dnb2[j], base[nbU[j] + k], a);
        dst[k] = fmul2(a, dd);
    }
}

// acc[0:18) += in @ W (36-wide output slice), weights broadcast from smem
template<int K, int RS>
__device__ __forceinline__ void mm1(const float* W0, const float* in, ull* acc) {
    #pragma unroll 2
    for (int k = 0; k < K; k++) {
        const float a = in[k];
        const ull q = pk2(a, a);
        const ulonglong2* w = (const ulonglong2*)(W0 + k * RS);
        #pragma unroll
        for (int jv = 0; jv < 9; jv++) {
            ulonglong2 ww = w[jv];
            acc[2 * jv]     = ffma2(q, ww.x, acc[2 * jv]);
            acc[2 * jv + 1] = ffma2(q, ww.y, acc[2 * jv + 1]);
        }
    }
}

// stats over out rows: Wf features x NS stripes
__device__ __forceinline__ void stat1(Smem& sm, int t, int Wf, int NS) {
    if (t < Wf * NS) {
        const int f = t % Wf, sI = t / Wf;
        float s = 0.f, s2 = 0.f;
        const float* pp = sm.out + f;
        for (int n = sI; n < SN; n += NS) { float v = pp[n * OSF]; s += v; s2 = fmaf(v, v, s2); }
        sm.redP[t] = s; sm.redQ[t] = s2;
    }
}

__device__ __forceinline__ void sc1(Smem& sm, int t, int Wf, int NS,
                                    const float* gv, const float* bev, const float* av) {
    const float invS = 1.0f / (float)SN;
    if (t < Wf) {
        float s = 0.f, s2 = 0.f;
        for (int i = 0; i < NS; i++) { s += sm.redP[t + i * Wf]; s2 += sm.redQ[t + i * Wf]; }
        float m = s * invS, af = av[t];
        float var = s2 * invS - m * m * af * (2.0f - af);
        float S = gv[t] * rsqrtf(var + EPSV);
        sm.redS[t] = S; sm.redC[t] = bev[t] - af * m * S;
    }
}

__global__ void __launch_bounds__(NT, 2) gnn_kernel(
    const int* __restrict__ x,
    const float* __restrict__ emb,
    const float* __restrict__ wc1, const float* __restrict__ bc1,
    const float* __restrict__ wc2, const float* __restrict__ bc2,
    const float* __restrict__ wc3, const float* __restrict__ bc3,
    const float* __restrict__ wr1, const float* __restrict__ br1,
    const float* __restrict__ wr2, const float* __restrict__ br2,
    const float* __restrict__ g1, const float* __restrict__ be1, const float* __restrict__ a1,
    const float* __restrict__ g2, const float* __restrict__ be2, const float* __restrict__ a2,
    const float* __restrict__ g3, const float* __restrict__ be3, const float* __restrict__ a3)
{
    extern __shared__ char smraw[];
    Smem& sm = *reinterpret_cast<Smem*>(smraw);
    const int t = threadIdx.x;
    const bool isNode = (t < SN);
    ull* const hU = (ull*)sm.h;
    const float invS = 1.0f / (float)SN;

    cp_sm(sm.wc3, wc3, 36 * 72, t);
    cp_sm(sm.wr2, wr2, 36 * 72, t);
    cp_sm(sm.wc2, wc2, 18 * 36, t);
    cp_sm(sm.wr1, wr1, 18 * 36, t);
    cp_sm(sm.bc1, bc1, 18, t);  cp_sm(sm.bc2, bc2, 36, t);  cp_sm(sm.bc3, bc3, 72, t);
    cp_sm(sm.br1, br1, 36, t);  cp_sm(sm.br2, br2, 72, t);
    cp_sm(sm.g1v, g1, 18, t);   cp_sm(sm.be1v, be1, 18, t); cp_sm(sm.a1v, a1, 18, t);
    cp_sm(sm.g2v, g2, 36, t);   cp_sm(sm.be2v, be2, 36, t); cp_sm(sm.a2v, a2, 36, t);
    cp_sm(sm.g3v, g3, 72, t);   cp_sm(sm.be3v, be3, 72, t); cp_sm(sm.a3v, a3, 72, t);
    cp_sm(sm.embs, emb, 3 * 18, t);

    if (t < 54) {
        const int e = t / 18, j = t % 18;
        float s = 0.f;
        #pragma unroll
        for (int k = 0; k < 18; k++) s += emb[e * 18 + k] * wc1[k * 18 + j];
        sm.E1[e * 18 + j] = s;
    }

    int nbU[6], nbi[6];
    ull dnb2[6];
    float disn = 0.f;
    if (isNode) {
        const int r = t / NBOARD, c = t % NBOARD;
        const int drr[6] = { -1, 1, 0, 0, -1, 1 };
        const int dcc[6] = { 0, 0, -1, 1, 1, -1 };
        int deg = 1;
        #pragma unroll
        for (int j = 0; j < 6; j++) {
            int rr = r + drr[j], cc = c + dcc[j];
            if (rr >= 0 && rr < NBOARD && cc >= 0 && cc < NBOARD) { nbi[j] = rr * NBOARD + cc; deg++; }
            else nbi[j] = t;
            nbU[j] = nbi[j] * HSU;
        }
        disn = rsqrtf((float)deg);
        sm.dis[t] = disn;
    }
    __syncthreads();
    if (isNode) {
        #pragma unroll
        for (int j = 0; j < 6; j++) {
            const float d = (nbi[j] == t) ? 0.f : sm.dis[nbi[j]];
            dnb2[j] = pk2(d, d);
        }
    }
    __syncthreads();

    const ull dd = pk2(disn, disn);
    float* const hA = sm.h + t * HSF;
    ull* const haU = hU + t * HSU;
    float* const oA = sm.out + t * OSF;

    // prefetch first graph's x (one int held across the loop — pressure-neutral)
    int xnext = 0;
    if (isNode) xnext = x[blockIdx.x * SN + t];

    for (int g = blockIdx.x; g < NG; g += GGRID) {

        // ---- lookup: h <- E1[x], original embedding in regs ----
        ull h0A[9];
        if (isNode) {
            const int xa = xnext;
            if (g + GGRID < NG) xnext = x[(g + GGRID) * SN + t];
            const ull* ea = (const ull*)&sm.embs[xa * 18];
            const ull* fa = (const ull*)&sm.E1[xa * 18];
            #pragma unroll
            for (int i = 0; i < 9; i++) { h0A[i] = ea[i]; haU[i] = fa[i]; }
        }
        __syncthreads();

        // ================= Layer 1: conv = gather(E1x) + bc1 ================
        if (isNode) {
            const ull* b1 = (const ull*)sm.bc1;
            ull aU[9];
            gatherU<9>(hU, haU, aU, nbU, dnb2, dd);
            ull* ouA = (ull*)oA;
            #pragma unroll
            for (int i = 0; i < 9; i++) ouA[i] = fadd2(aU[i], b1[i]);
        }
        __syncthreads();
        stat1(sm, t, 18, 10);
        __syncthreads();
        sc1(sm, t, 18, 10, sm.g1v, sm.be1v, sm.a1v);
        __syncthreads();
        if (isNode) {
            const ull* ouA = (const ull*)oA;
            const ull* Su = (const ull*)sm.redS;
            const ull* Cu = (const ull*)sm.redC;
            #pragma unroll
            for (int i = 0; i < 9; i++)
                haU[i] = fadd2(ffma2(ouA[i], Su[i], Cu[i]), h0A[i]);
        }
        __syncthreads();

        // ================= Layer 2 (18->36) =================================
        ull accR[18];
        if (isNode) {
            gatherU<9>(hU, haU, haU + AOFFU, nbU, dnb2, dd);
            ull acc[18];
            const ull* b2 = (const ull*)sm.bc2;
            #pragma unroll
            for (int i = 0; i < 18; i++) acc[i] = b2[i];
            mm1<18, 36>(sm.wc2, hA + AOFF, acc);
            ull* ouA = (ull*)oA;
            #pragma unroll
            for (int i = 0; i < 18; i++) ouA[i] = acc[i];
            const ull* r1 = (const ull*)sm.br1;
            #pragma unroll
            for (int i = 0; i < 18; i++) accR[i] = r1[i];
            mm1<18, 36>(sm.wr1, hA, accR);
        }
        __syncthreads();
        stat1(sm, t, 36, 5);
        __syncthreads();
        sc1(sm, t, 36, 5, sm.g2v, sm.be2v, sm.a2v);
        __syncthreads();
        if (isNode) {
            const ull* ouA = (const ull*)oA;
            const ull* Su = (const ull*)sm.redS;
            const ull* Cu = (const ull*)sm.redC;
            #pragma unroll
            for (int i = 0; i < 18; i++)
                haU[i] = fadd2(ffma2(ouA[i], Su[i], Cu[i]), accR[i]);
        }
        __syncthreads();

        // ========== Layer 3 (36->72): merged single pipeline ================
        // conv half0 -> out rows; conv half1 -> AGG region (dead after convs).
        if (isNode) {
            gatherU<18>(hU, haU, haU + AOFFU, nbU, dnb2, dd);
            {
                ull acc[18];
                const ull* b3 = (const ull*)&sm.bc3[0];
                #pragma unroll
                for (int i = 0; i < 18; i++) acc[i] = b3[i];
                mm1<36, 72>(sm.wc3, hA + AOFF, acc);
                ull* ouA = (ull*)oA;
                #pragma unroll
                for (int i = 0; i < 18; i++) ouA[i] = acc[i];
            }
            {
                ull acc[18];
                const ull* b3 = (const ull*)&sm.bc3[36];
                #pragma unroll
                for (int i = 0; i < 18; i++) acc[i] = b3[i];
                mm1<36, 72>(sm.wc3 + 36, hA + AOFF, acc);
                ull* gAo = haU + AOFFU;
                #pragma unroll
                for (int i = 0; i < 18; i++) gAo[i] = acc[i];
            }
        }
        __syncthreads();
        // 72-wide stats, 2 stripes (144 threads)
        if (t < 144) {
            const int f = t % 72, sI = t / 72;
            const float* pp = (f < 36) ? (sm.out + f) : (sm.h + AOFF + (f - 36));
            const int str = (f < 36) ? OSF : HSF;
            float s = 0.f, s2 = 0.f;
            for (int n = sI; n < SN; n += 2) { float v = pp[n * str]; s += v; s2 = fmaf(v, v, s2); }
            sm.redP[t] = s; sm.redQ[t] = s2;
        }
        __syncthreads();
        if (t < 72) {
            float s = sm.redP[t] + sm.redP[t + 72];
            float s2 = sm.redQ[t] + sm.redQ[t + 72];
            float m = s * invS, af = sm.a3v[t];
            float var = s2 * invS - m * m * af * (2.0f - af);
            float S = sm.g3v[t] * rsqrtf(var + EPSV);
            sm.redS[t] = S; sm.redC[t] = sm.be3v[t] - af * m * S;
        }
        __syncthreads();
        // resid + apply, both halves (FEAT region intact as input)
        if (isNode) {
            {
                ull aR[18];
                const ull* r2 = (const ull*)&sm.br2[0];
                #pragma unroll
                for (int i = 0; i < 18; i++) aR[i] = r2[i];
                mm1<36, 72>(sm.wr2, hA, aR);
                ull* ouA = (ull*)oA;
                const ull* SA = (const ull*)sm.redS;
                const ull* CA = (const ull*)sm.redC;
                #pragma unroll
                for (int i = 0; i < 18; i++)
                    ouA[i] = fadd2(ffma2(ouA[i], SA[i], CA[i]), aR[i]);
            }
            {
                ull aR[18];
                const ull* r2 = (const ull*)&sm.br2[36];
                #pragma unroll
                for (int i = 0; i < 18; i++) aR[i] = r2[i];
                mm1<36, 72>(sm.wr2 + 36, hA, aR);
                ull* gAo = haU + AOFFU;
                const ull* SA = (const ull*)&sm.redS[36];
                const ull* CA = (const ull*)&sm.redC[36];
                #pragma unroll
                for (int i = 0; i < 18; i++)
                    gAo[i] = fadd2(ffma2(gAo[i], SA[i], CA[i]), aR[i]);
            }
        }
        __syncthreads();
        // pool: 2-stripe partials then final write
        if (t < 144) {
            const int f = t % 72, sI = t / 72;
            const float* pp = (f < 36) ? (sm.out + f) : (sm.h + AOFF + (f - 36));
            const int str = (f < 36) ? OSF : HSF;
            float m = -INFINITY;
            for (int n = sI; n < SN; n += 2) m = fmaxf(m, pp[n * str]);
            sm.redP[t] = m;
        }
        __syncthreads();
        if (t < 72) g_pooled[g * 72 + t] = fmaxf(sm.redP[t], sm.redP[t + 72]);
        __syncthreads();
    }
}

// ---------------------------------------------------------------------------
// MLP (proven 34.9us): TM=8, grid 256, 512 thr, split-k z2.
// ---------------------------------------------------------------------------
struct __align__(16) MSmem {
    ull rowsT[72][5];
    ull z1T[512][5];
    ull z2P[256][5];
    ull z2T[256][5];
};

__global__ void __launch_bounds__(512, 2) mlp_kernel(
    const float* __restrict__ wf1, const float* __restrict__ bf1,
    const float* __restrict__ wf2, const float* __restrict__ bf2,
    const float* __restrict__ wm, const float* __restrict__ bm,
    const float* __restrict__ wl, const float* __restrict__ bl,
    float* __restrict__ out)
{
    extern __shared__ char smraw[];
    MSmem& sm = *reinterpret_cast<MSmem*>(smraw);
    const int tid = threadIdx.x;
    const int r0 = blockIdx.x * 8;

    {
        float* rf = (float*)sm.rowsT;
        for (int i = tid; i < 8 * 72; i += 512) {
            const int k = i / 8, r = i % 8;
            rf[k * 10 + r] = g_pooled[(r0 + r) * 72 + k];
        }
    }
    __syncthreads();

    {
        const int j = tid;
        const float b = __ldg(bf1 + j);
        ull acc[4];
        #pragma unroll
        for (int i = 0; i < 4; i++) acc[i] = pk2(b, b);
        #pragma unroll 8
        for (int k = 0; k < 72; k++) {
            const float w = __ldg(wf1 + k * 512 + j);
            const ull ww = pk2(w, w);
            const ull* rw = sm.rowsT[k];
            #pragma unroll
            for (int i = 0; i < 4; i++) acc[i] = ffma2(ww, rw[i], acc[i]);
        }
        #pragma unroll
        for (int i = 0; i < 4; i++) {
            float2 v = upk2(acc[i]);
            sm.z1T[j][i] = pk2(fmaxf(v.x, 0.f), fmaxf(v.y, 0.f));
        }
    }
    __syncthreads();

    {
        const int jj = tid & 255, half = tid >> 8;
        ull acc[4];
        if (half == 0) {
            const float b = __ldg(bf2 + jj);
            #pragma unroll
            for (int i = 0; i < 4; i++) acc[i] = pk2(b, b);
        } else {
            #pragma unroll
            for (int i = 0; i < 4; i++) acc[i] = 0ull;
        }
        const int k0 = half * 256;
        #pragma unroll 8
        for (int kk = 0; kk < 256; kk++) {
            const int k = k0 + kk;
            const float w = __ldg(wf2 + k * 256 + jj);
            const ull ww = pk2(w, w);
            const ull* zw = sm.z1T[k];
            #pragma unroll
            for (int i = 0; i < 4; i++) acc[i] = ffma2(ww, zw[i], acc[i]);
        }
        if (half == 1) {
            #pragma unroll
            for (int i = 0; i < 4; i++) sm.z2P[jj][i] = acc[i];
        }
        __syncthreads();
        if (half == 0) {
            #pragma unroll
            for (int i = 0; i < 4; i++) {
                float2 v = upk2(fadd2(acc[i], sm.z2P[jj][i]));
                sm.z2T[jj][i] = pk2(fmaxf(v.x, 0.f), fmaxf(v.y, 0.f));
            }
        }
        __syncthreads();
    }

    {
        const int w = tid >> 5, lane = tid & 31;
        if (w < 8) {
            const int rp = w >> 1, hi = w & 1;
            float smv = 0.f, slv = 0.f;
            #pragma unroll 4
            for (int k = lane; k < 256; k += 32) {
                float2 v2 = upk2(sm.z2T[k][rp]);
                const float v = hi ? v2.y : v2.x;
                smv = fmaf(v, __ldg(wm + k), smv);
                slv = fmaf(v, __ldg(wl + k), slv);
            }
            #pragma unroll
            for (int o = 16; o > 0; o >>= 1) {
                smv += __shfl_xor_sync(0xffffffffu, smv, o);
                slv += __shfl_xor_sync(0xffffffffu, slv, o);
            }
            if (lane == 0) {
                out[r0 + w] = smv + __ldg(bm);
                const float ls = tanhf(slv + __ldg(bl));
                out[NG + r0 + w] = LSMIN + 0.5f * (LSMAX - LSMIN) * (ls + 1.0f);
            }
        }
    }
}

// ---------------------------------------------------------------------------
extern "C" void kernel_launch(void* const* d_in, const int* in_sizes, int n_in,
                              void* d_out, int out_size)
{
    const int*   x    = (const int*)d_in[0];
    const float* emb  = (const float*)d_in[2];
    const float* wc1  = (const float*)d_in[3];
    const float* bc1  = (const float*)d_in[4];
    const float* wc2  = (const float*)d_in[5];
    const float* bc2  = (const float*)d_in[6];
    const float* wc3  = (const float*)d_in[7];
    const float* bc3  = (const float*)d_in[8];
    const float* wr1  = (const float*)d_in[9];
    const float* br1  = (const float*)d_in[10];
    const float* wr2  = (const float*)d_in[11];
    const float* br2  = (const float*)d_in[12];
    const float* g1   = (const float*)d_in[13];
    const float* be1  = (const float*)d_in[14];
    const float* a1   = (const float*)d_in[15];
    const float* g2   = (const float*)d_in[16];
    const float* be2  = (const float*)d_in[17];
    const float* a2   = (const float*)d_in[18];
    const float* g3   = (const float*)d_in[19];
    const float* be3  = (const float*)d_in[20];
    const float* a3   = (const float*)d_in[21];
    const float* wf1  = (const float*)d_in[22];
    const float* bf1  = (const float*)d_in[23];
    const float* wf2  = (const float*)d_in[24];
    const float* bf2  = (const float*)d_in[25];
    const float* wm   = (const float*)d_in[26];
    const float* bm   = (const float*)d_in[27];
    const float* wl   = (const float*)d_in[28];
    const float* bl   = (const float*)d_in[29];
    float* out = (float*)d_out;

    cudaFuncSetAttribute(gnn_kernel, cudaFuncAttributeMaxDynamicSharedMemorySize,
                         (int)sizeof(Smem));
    cudaFuncSetAttribute(mlp_kernel, cudaFuncAttributeMaxDynamicSharedMemorySize,
                         (int)sizeof(MSmem));

    gnn_kernel<<<GGRID, NT, sizeof(Smem)>>>(
        x, emb, wc1, bc1, wc2, bc2, wc3, bc3, wr1, br1, wr2, br2,
        g1, be1, a1, g2, be2, a2, g3, be3, a3);

    mlp_kernel<<<NG / 8, 512, sizeof(MSmem)>>>(
        wf1, bf1, wf2, bf2, wm, bm, wl, bl, out);
}